// round 4
// baseline (speedup 1.0000x reference)
#include <cuda_runtime.h>
#include <cuda_bf16.h>

// Problem constants (fixed shapes for this problem)
#define NN 100000
#define NE 1600000

// ---------------- scratch (device globals; referenced ONLY from device code)
__device__ float g_H[(size_t)NN * 128];    // GEMM output / agg input
__device__ float g_G[(size_t)NN * 128];    // agg output / next GEMM input
__device__ int   g_deg[NN];
__device__ int   g_rowptr[NN + 1];
__device__ int   g_cursor[NN];
__device__ int   g_col[NE];
__device__ float g_dinv[NN];
__device__ int   g_scantmp[NN];
__device__ int   g_bsums[128];

// ---------------- graph prep -----------------------------------------------
__global__ void k_zero_deg(int n) {
    int i = blockIdx.x * blockDim.x + threadIdx.x;
    if (i < n) g_deg[i] = 0;
}

__global__ void k_count(const int* __restrict__ dst, int e) {
    int i = blockIdx.x * blockDim.x + threadIdx.x;
    if (i < e) atomicAdd(&g_deg[dst[i]], 1);
}

__global__ void k_scan_block(int n) {
    int tid = threadIdx.x, lane = tid & 31, wid = tid >> 5;
    int i = blockIdx.x * 1024 + tid;
    int v = (i < n) ? g_deg[i] : 0;
    #pragma unroll
    for (int o = 1; o < 32; o <<= 1) {
        int t = __shfl_up_sync(0xffffffffu, v, o);
        if (lane >= o) v += t;
    }
    __shared__ int ws[32];
    if (lane == 31) ws[wid] = v;
    __syncthreads();
    if (wid == 0) {
        int w = ws[lane];
        #pragma unroll
        for (int o = 1; o < 32; o <<= 1) {
            int t = __shfl_up_sync(0xffffffffu, w, o);
            if (lane >= o) w += t;
        }
        ws[lane] = w;
    }
    __syncthreads();
    if (wid > 0) v += ws[wid - 1];
    if (i < n) g_scantmp[i] = v;
    if (tid == 1023) g_bsums[blockIdx.x] = v;
}

__global__ void k_scan_sums(int nb) {
    if (threadIdx.x == 0 && blockIdx.x == 0) {
        int acc = 0;
        for (int b = 0; b < nb; b++) {
            int t = g_bsums[b];
            g_bsums[b] = acc;
            acc += t;
        }
    }
}

__global__ void k_finalize(int n) {
    int i = blockIdx.x * 1024 + threadIdx.x;
    if (i >= n) return;
    int incl = g_scantmp[i] + g_bsums[blockIdx.x];
    int d = g_deg[i];
    int excl = incl - d;
    g_cursor[i] = excl;
    g_rowptr[i] = excl;
    if (i == n - 1) g_rowptr[n] = incl;
    g_dinv[i] = rsqrtf((float)(d + 1));  // +1: self-loop
}

__global__ void k_scatter(const int* __restrict__ src,
                          const int* __restrict__ dst, int e) {
    int i = blockIdx.x * blockDim.x + threadIdx.x;
    if (i < e) {
        int d = dst[i];
        int p = atomicAdd(&g_cursor[d], 1);
        g_col[p] = src[i];
    }
}

// ---------------- GEMM: C[M,NA] = A[M,128] @ W[128,NA] ---------------------
// Scratch buffers selected by template flags; only harness pointers are args.
// A_SEL: 0 = param, 1 = g_G.   C is always g_H.
template <int BN, int TX, int RPT, int A_SEL>
__global__ void gemm_k(const float* __restrict__ Ap, const float* __restrict__ W,
                       int M, int NA, int ldc) {
    const float* __restrict__ A = (A_SEL == 0) ? Ap : (const float*)g_G;
    float* __restrict__ C = (float*)g_H;
    constexpr int BM = 64, BK = 32, K = 128;
    __shared__ float As[BM][BK];
    __shared__ float Ws[BK][BN];
    int tid = threadIdx.x;
    int tx = tid % TX;        // col group (4 cols)
    int ty = tid / TX;        // row group (RPT rows)
    int rowBase = blockIdx.x * BM;

    float acc[RPT][4];
    #pragma unroll
    for (int i = 0; i < RPT; i++)
        #pragma unroll
        for (int j = 0; j < 4; j++) acc[i][j] = 0.f;

    for (int kt = 0; kt < K; kt += BK) {
        #pragma unroll
        for (int t = 0; t < (BM * BK) / 256; t++) {
            int idx = tid + t * 256;
            int r = idx / BK, kk = idx % BK;
            int gr = rowBase + r;
            As[r][kk] = (gr < M) ? A[(size_t)gr * K + kt + kk] : 0.f;
        }
        #pragma unroll
        for (int t = 0; t < (BK * BN) / 256; t++) {
            int idx = tid + t * 256;
            int r = idx / BN, c = idx % BN;
            Ws[r][c] = (c < NA) ? W[(kt + r) * NA + c] : 0.f;
        }
        __syncthreads();
        #pragma unroll
        for (int kk = 0; kk < BK; kk++) {
            float b0 = Ws[kk][tx * 4 + 0];
            float b1 = Ws[kk][tx * 4 + 1];
            float b2 = Ws[kk][tx * 4 + 2];
            float b3 = Ws[kk][tx * 4 + 3];
            #pragma unroll
            for (int i = 0; i < RPT; i++) {
                float a = As[ty * RPT + i][kk];
                acc[i][0] += a * b0;
                acc[i][1] += a * b1;
                acc[i][2] += a * b2;
                acc[i][3] += a * b3;
            }
        }
        __syncthreads();
    }
    #pragma unroll
    for (int i = 0; i < RPT; i++) {
        int gr = rowBase + ty * RPT + i;
        if (gr >= M) continue;
        if constexpr (BN == 128) {
            float4 v = make_float4(acc[i][0], acc[i][1], acc[i][2], acc[i][3]);
            *(float4*)&C[(size_t)gr * ldc + tx * 4] = v;
        } else {
            #pragma unroll
            for (int j = 0; j < 4; j++) {
                int c = tx * 4 + j;
                if (c < NA) C[(size_t)gr * ldc + c] = acc[i][j];
            }
        }
    }
}

// ---------------- aggregation, F=128 (one warp per node) -------------------
// Reads g_H, writes g_G. Only bias is a kernel arg.
__global__ void agg128_k(const float* __restrict__ bias, int relu, int n) {
    int node = blockIdx.x * (blockDim.x >> 5) + (threadIdx.x >> 5);
    if (node >= n) return;
    int lane = threadIdx.x & 31;
    const float4* __restrict__ H4 = (const float4*)g_H;
    float* __restrict__ O = (float*)g_G;
    float di = g_dinv[node];
    float4 h = H4[(size_t)node * 32 + lane];
    float ax = di * h.x, ay = di * h.y, az = di * h.z, aw = di * h.w;  // self-loop
    int p = g_rowptr[node], pend = g_rowptr[node + 1];
    for (; p < pend; p++) {
        int s = g_col[p];
        float ds = g_dinv[s];
        float4 hs = H4[(size_t)s * 32 + lane];
        ax += ds * hs.x; ay += ds * hs.y; az += ds * hs.z; aw += ds * hs.w;
    }
    float4 bv = ((const float4*)bias)[lane];
    float ox = di * ax + bv.x, oy = di * ay + bv.y;
    float oz = di * az + bv.z, ow = di * aw + bv.w;
    if (relu) {
        ox = fmaxf(ox, 0.f); oy = fmaxf(oy, 0.f);
        oz = fmaxf(oz, 0.f); ow = fmaxf(ow, 0.f);
    }
    ((float4*)O)[(size_t)node * 32 + lane] = make_float4(ox, oy, oz, ow);
}

// ---------------- aggregation, F=40 (one warp per node) --------------------
// Reads g_H (ld=40), writes harness output pointer.
__global__ void agg40_k(const float* __restrict__ bias, float* __restrict__ O, int n) {
    int node = blockIdx.x * (blockDim.x >> 5) + (threadIdx.x >> 5);
    if (node >= n) return;
    int lane = threadIdx.x & 31;
    const float* __restrict__ H = (const float*)g_H;
    bool hi = (lane < 8);
    float di = g_dinv[node];
    float a0 = di * H[(size_t)node * 40 + lane];
    float a1 = hi ? di * H[(size_t)node * 40 + 32 + lane] : 0.f;
    int p = g_rowptr[node], pend = g_rowptr[node + 1];
    for (; p < pend; p++) {
        int s = g_col[p];
        float ds = g_dinv[s];
        a0 += ds * H[(size_t)s * 40 + lane];
        if (hi) a1 += ds * H[(size_t)s * 40 + 32 + lane];
    }
    O[(size_t)node * 40 + lane] = di * a0 + bias[lane];
    if (hi) O[(size_t)node * 40 + 32 + lane] = di * a1 + bias[32 + lane];
}

// ---------------- launch ----------------------------------------------------
// No CUDA runtime API calls here except kernel launches.
extern "C" void kernel_launch(void* const* d_in, const int* in_sizes, int n_in,
                              void* d_out, int out_size) {
    const float* x   = (const float*)d_in[0];
    const int*   ei  = (const int*)d_in[1];    // int32! (JAX x64 disabled)
    const float* W1  = (const float*)d_in[2];
    const float* b1  = (const float*)d_in[3];
    const float* Wm  = (const float*)d_in[4];
    const float* bm  = (const float*)d_in[5];
    const float* W2  = (const float*)d_in[6];
    const float* b2  = (const float*)d_in[7];
    float* out = (float*)d_out;

    const int n = NN, e = NE;
    const int* src = ei;        // edge_index[0, :]
    const int* dst = ei + e;    // edge_index[1, :]

    const int scanBlocks = (n + 1023) / 1024;   // 98

    // graph prep
    k_zero_deg<<<(n + 255) / 256, 256>>>(n);
    k_count<<<(e + 255) / 256, 256>>>(dst, e);
    k_scan_block<<<scanBlocks, 1024>>>(n);
    k_scan_sums<<<1, 32>>>(scanBlocks);
    k_finalize<<<scanBlocks, 1024>>>(n);
    k_scatter<<<(e + 255) / 256, 256>>>(src, dst, e);

    const int gemmBlocks = (n + 63) / 64;       // 1563
    const int aggBlocks  = (n + 7) / 8;         // warp per node, 8 warps/block

    // layer 1: g_H = x @ W1; g_G = relu(agg(g_H) + b1)
    gemm_k<128, 32, 8, 0><<<gemmBlocks, 256>>>(x, W1, n, 128, 128);
    agg128_k<<<aggBlocks, 256>>>(b1, 1, n);

    // layer 2: g_H = g_G @ Wm; g_G = relu(agg(g_H) + bm)
    gemm_k<128, 32, 8, 1><<<gemmBlocks, 256>>>(nullptr, Wm, n, 128, 128);
    agg128_k<<<aggBlocks, 256>>>(bm, 1, n);

    // layer 3: g_H[:, :40] = g_G @ W2; out = agg(g_H) + b2 (no relu)
    gemm_k<64, 16, 4, 1><<<gemmBlocks, 256>>>(nullptr, W2, n, 40, 40);
    agg40_k<<<aggBlocks, 256>>>(b2, out, n);
}